// round 3
// baseline (speedup 1.0000x reference)
#include <cuda_runtime.h>
#include <math.h>

#define BB 64
#define CC 32
#define HH 16
#define VV 4096
#define NMAX 16384
#define CHK 256          // codes per smem chunk
#define NCHUNK (VV/CHK)  // 16

// ---------------- scratch (no allocation allowed) ----------------
__device__ float g_fhat[BB*CC*HH*HH];     // 524288
__device__ float g_rest[NMAX*CC];         // pooled residual vectors [n][c]
__device__ float g_esq[VV];
__device__ float g_d1[NCHUNK*NMAX];
__device__ int   g_i1[NCHUNK*NMAX];
__device__ int   g_idx[NMAX];
__device__ float g_loss;

// ---------------- init ----------------
__global__ void k_zero() {
    int i = blockIdx.x*blockDim.x + threadIdx.x;
    if (i < BB*CC*HH*HH) g_fhat[i] = 0.f;
    if (i == 0) g_loss = 0.f;
}

__global__ void k_esq(const float* __restrict__ embed) {
    int v = blockIdx.x*blockDim.x + threadIdx.x;
    if (v < VV) {
        const float4* e4 = (const float4*)(embed + v*32);
        float s = 0.f;
        #pragma unroll
        for (int q = 0; q < 8; q++) {
            float4 a = e4[q];
            s = fmaf(a.x, a.x, s); s = fmaf(a.y, a.y, s);
            s = fmaf(a.z, a.z, s); s = fmaf(a.w, a.w, s);
        }
        g_esq[v] = s;
    }
}

// ---------------- residual + adaptive avg pool -> g_rest[n][c] ----------------
__global__ void k_pool(const float* __restrict__ f, int pn, int N) {
    int t = blockIdx.x*blockDim.x + threadIdx.x;
    if (t >= N*CC) return;
    int c = t & 31, n = t >> 5;
    int pp = pn*pn;
    int b = n / pp, r = n % pp, i = r / pn, j = r % pn;
    int s0 = (i*HH)/pn,  e0 = ((i+1)*HH + pn - 1)/pn;
    int s1 = (j*HH)/pn,  e1 = ((j+1)*HH + pn - 1)/pn;
    const float* fb = f      + ((b*CC + c) << 8);
    const float* hb = g_fhat + ((b*CC + c) << 8);
    float s = 0.f;
    for (int h = s0; h < e0; h++)
        for (int w = s1; w < e1; w++)
            s += fb[h*16 + w] - hb[h*16 + w];
    g_rest[n*32 + c] = s / (float)((e0 - s0) * (e1 - s1));
}

// ---------------- argmin phase 1: per-chunk best ----------------
__global__ __launch_bounds__(256) void k_dist(const float* __restrict__ embed, int N) {
    __shared__ float4 es4[CHK*8];   // 32 KB
    __shared__ float  ess[CHK];     // 1 KB
    int ck = blockIdx.y;
    int t  = threadIdx.x;
    {
        const float4* src = (const float4*)(embed + (ck*CHK)*32);
        for (int q = t; q < CHK*8; q += 256) es4[q] = src[q];
        if (t < CHK) ess[t] = g_esq[ck*CHK + t];
    }
    int n0 = blockIdx.x*512 + t;
    int n1 = n0 + 256;
    bool v0 = (n0 < N), v1 = (n1 < N);
    float4 x0[8], x1[8];
    #pragma unroll
    for (int q = 0; q < 8; q++) { x0[q] = make_float4(0,0,0,0); x1[q] = x0[q]; }
    if (v0) { const float4* xp = (const float4*)(g_rest + n0*32);
        #pragma unroll
        for (int q = 0; q < 8; q++) x0[q] = xp[q]; }
    if (v1) { const float4* xp = (const float4*)(g_rest + n1*32);
        #pragma unroll
        for (int q = 0; q < 8; q++) x1[q] = xp[q]; }
    __syncthreads();
    if (!v0) return;
    float bd0 = 3.4e38f, bd1 = 3.4e38f;
    int   bi0 = 0,        bi1 = 0;
    for (int v = 0; v < CHK; v++) {
        float d0 = 0.f, d1 = 0.f;
        #pragma unroll
        for (int q = 0; q < 8; q++) {
            float4 e = es4[v*8 + q];
            d0 = fmaf(x0[q].x, e.x, d0); d0 = fmaf(x0[q].y, e.y, d0);
            d0 = fmaf(x0[q].z, e.z, d0); d0 = fmaf(x0[q].w, e.w, d0);
            d1 = fmaf(x1[q].x, e.x, d1); d1 = fmaf(x1[q].y, e.y, d1);
            d1 = fmaf(x1[q].z, e.z, d1); d1 = fmaf(x1[q].w, e.w, d1);
        }
        float es = ess[v];
        float dist0 = es - 2.f*d0;
        float dist1 = es - 2.f*d1;
        if (dist0 < bd0) { bd0 = dist0; bi0 = v; }
        if (dist1 < bd1) { bd1 = dist1; bi1 = v; }
    }
    g_d1[ck*NMAX + n0] = bd0;  g_i1[ck*NMAX + n0] = ck*CHK + bi0;
    if (v1) { g_d1[ck*NMAX + n1] = bd1;  g_i1[ck*NMAX + n1] = ck*CHK + bi1; }
}

// ---------------- argmin phase 2: reduce chunks (first-occurrence tie-break) ----------------
__global__ void k_amin(int N) {
    int n = blockIdx.x*blockDim.x + threadIdx.x;
    if (n >= N) return;
    float bd = g_d1[n]; int bi = g_i1[n];
    #pragma unroll
    for (int ck = 1; ck < NCHUNK; ck++) {
        float d = g_d1[ck*NMAX + n];
        if (d < bd) { bd = d; bi = g_i1[ck*NMAX + n]; }
    }
    g_idx[n] = bi;
}

// ---------------- gather + bilinear upsample + Phi conv + f_hat accum + loss ----------------
// grid = 128 blocks (2 per image: rows 0..7 / 8..15), 256 threads
__global__ __launch_bounds__(256) void k_phi(
    const float* __restrict__ f, const float* __restrict__ embed,
    const float* __restrict__ phi_w, const float* __restrict__ phi_b,
    int pn, int kidx)
{
    extern __shared__ float sm[];
    float* hpn = sm;            // 8192 floats  [p][c]
    float* hs  = sm + 8192;     // 5760 floats  [c][10][18]  (zero padded)
    float* ws  = hs + 5760;     // 9216 floats  [ci][dy][dx][co]
    float* red = ws + 9216;     // 256
    int t  = threadIdx.x;
    int b  = blockIdx.x >> 1;
    int r0 = (blockIdx.x & 1) * 8;
    int np = pn*pn;

    // weights: transpose OIHW -> [ci][dy][dx][co]
    for (int q = t; q < 9216; q += 256) {
        int co = q & 31, u = q >> 5;
        int dx = u % 3, dy = (u/3) % 3, ci = u/9;
        ws[q] = phi_w[kidx*9216 + ((co*32 + ci)*9 + dy*3 + dx)];
    }
    // gather selected codes
    for (int p = t; p < np; p += 256) {
        int id = g_idx[b*np + p];
        const float4* src = (const float4*)(embed + id*32);
        float4* dst = (float4*)(hpn + p*32);
        #pragma unroll
        for (int q = 0; q < 8; q++) dst[q] = src[q];
    }
    // zero padded tile
    for (int q = t; q < 5760; q += 256) hs[q] = 0.f;
    __syncthreads();

    // bilinear upsample (half-pixel, edge clamp) rows r0-1..r0+8 -> hs rows 0..9, cols 1..16
    if (t < 160) {
        int lr = t >> 4;       // 0..9
        int x  = t & 15;
        int gy = r0 - 1 + lr;
        if (gy >= 0 && gy < 16) {
            float sc = pn * 0.0625f;
            float sy = (gy + 0.5f) * sc - 0.5f;
            float y0f = floorf(sy);
            float fy = sy - y0f;
            int y0 = (int)y0f, y1i = y0 + 1;
            y0  = min(max(y0, 0), pn-1);
            y1i = min(max(y1i, 0), pn-1);
            float sx = (x + 0.5f) * sc - 0.5f;
            float x0f = floorf(sx);
            float fx = sx - x0f;
            int xx0 = (int)x0f, xx1 = xx0 + 1;
            xx0 = min(max(xx0, 0), pn-1);
            xx1 = min(max(xx1, 0), pn-1);
            float w00 = (1.f-fy)*(1.f-fx), w01 = (1.f-fy)*fx;
            float w10 = fy*(1.f-fx),       w11 = fy*fx;
            const float* p00 = hpn + (y0 *pn + xx0)*32;
            const float* p01 = hpn + (y0 *pn + xx1)*32;
            const float* p10 = hpn + (y1i*pn + xx0)*32;
            const float* p11 = hpn + (y1i*pn + xx1)*32;
            for (int c = 0; c < 32; c++) {
                float v = w00*p00[c] + w01*p01[c] + w10*p10[c] + w11*p11[c];
                hs[c*180 + lr*18 + (x+1)] = v;
            }
        }
    }
    __syncthreads();

    // conv3x3 (cross-correlation, zero pad) for 16 output channels per thread
    int px = t & 127;
    int ty = px >> 4, tx = px & 15;
    int co0 = (t >> 7) * 16;
    float acc[16];
    #pragma unroll
    for (int q = 0; q < 16; q++) acc[q] = phi_b[kidx*32 + co0 + q];
    for (int ci = 0; ci < 32; ci++) {
        #pragma unroll
        for (int dy = 0; dy < 3; dy++) {
            #pragma unroll
            for (int dx = 0; dx < 3; dx++) {
                float hv = hs[ci*180 + (ty+dy)*18 + (tx+dx)];
                const float4* w4 = (const float4*)(ws + ((ci*3+dy)*3+dx)*32 + co0);
                #pragma unroll
                for (int q4 = 0; q4 < 4; q4++) {
                    float4 w = w4[q4];
                    acc[q4*4+0] = fmaf(hv, w.x, acc[q4*4+0]);
                    acc[q4*4+1] = fmaf(hv, w.y, acc[q4*4+1]);
                    acc[q4*4+2] = fmaf(hv, w.z, acc[q4*4+2]);
                    acc[q4*4+3] = fmaf(hv, w.w, acc[q4*4+3]);
                }
            }
        }
    }
    // phi = 0.5*h + 0.5*(conv+b); accumulate f_hat; loss sse
    int y = r0 + ty;
    float sse = 0.f;
    #pragma unroll
    for (int q = 0; q < 16; q++) {
        int co = co0 + q;
        float hu = hs[co*180 + (ty+1)*18 + (tx+1)];
        float hphi = 0.5f*hu + 0.5f*acc[q];
        int off = ((b*32 + co) << 8) + y*16 + tx;
        float fh = g_fhat[off] + hphi;
        g_fhat[off] = fh;
        float d = fh - f[off];
        sse = fmaf(d, d, sse);
    }
    red[t] = sse;
    __syncthreads();
    for (int s = 128; s > 0; s >>= 1) {
        if (t < s) red[t] += red[t + s];
        __syncthreads();
    }
    if (t == 0) atomicAdd(&g_loss, red[0]);
}

// ---------------- output ----------------
__global__ void k_out(float* __restrict__ out, int out_size) {
    int i = blockIdx.x*blockDim.x + threadIdx.x;
    if (i < out_size && i < BB*CC*HH*HH) out[i] = g_fhat[i];
    if (i == 0) {
        float lv = g_loss * (1.25f / (8.0f * 524288.0f));
        if (out_size > BB*CC*HH*HH) out[BB*CC*HH*HH] = lv;
        else if (out_size == 1)     out[0] = lv;
    }
}

// ---------------- launch ----------------
extern "C" void kernel_launch(void* const* d_in, const int* in_sizes, int n_in,
                              void* d_out, int out_size) {
    const float* f     = (const float*)d_in[0];
    const float* embed = (const float*)d_in[1];
    const float* phi_w = (const float*)d_in[2];
    const float* phi_b = (const float*)d_in[3];
    (void)in_sizes; (void)n_in;

    const int smem_phi = (8192 + 5760 + 9216 + 256) * 4;  // 93696 B
    cudaFuncSetAttribute(k_phi, cudaFuncAttributeMaxDynamicSharedMemorySize, smem_phi);

    static const int pns[8] = {1, 2, 4, 6, 8, 10, 13, 16};
    static const int kk [8] = {0, 0, 1, 1, 2, 2, 3, 3};

    k_zero<<<2048, 256>>>();
    k_esq<<<16, 256>>>(embed);

    for (int si = 0; si < 8; si++) {
        int pn = pns[si];
        int N  = BB * pn * pn;
        k_pool<<<(N*CC + 255)/256, 256>>>(f, pn, N);
        dim3 g1((N + 511)/512, NCHUNK);
        k_dist<<<g1, 256>>>(embed, N);
        k_amin<<<(N + 255)/256, 256>>>(N);
        k_phi<<<128, 256, smem_phi>>>(f, embed, phi_w, phi_b, pn, kk[si]);
    }
    k_out<<<2049, 256>>>((float*)d_out, out_size);
}

// round 4
// speedup vs baseline: 1.6053x; 1.6053x over previous
#include <cuda_runtime.h>
#include <math.h>

#define BB 64
#define CC 32
#define HH 16
#define VV 4096
#define NMAX 16384

typedef unsigned long long u64;

// ---------------- scratch (no allocation allowed) ----------------
__device__ float g_fhat[BB*CC*HH*HH];     // 524288
__device__ float g_rest[NMAX*CC];         // pooled residual vectors [n][c]
__device__ float g_esq[VV];
__device__ float g_d1[32*NMAX];           // up to 32 chunks
__device__ int   g_i1[32*NMAX];
__device__ int   g_idx[NMAX];
__device__ float g_loss;

// ---------------- f32x2 helpers ----------------
__device__ __forceinline__ void fma2(u64& acc, u64 a, u64 b) {
    asm("fma.rn.f32x2 %0, %1, %2, %0;" : "+l"(acc) : "l"(a), "l"(b));
}
__device__ __forceinline__ u64 pk2(float lo, float hi) {
    u64 r; asm("mov.b64 %0, {%1,%2};" : "=l"(r) : "f"(lo), "f"(hi)); return r;
}
__device__ __forceinline__ float2 upk2(u64 v) {
    float2 f; asm("mov.b64 {%0,%1}, %2;" : "=f"(f.x), "=f"(f.y) : "l"(v)); return f;
}

// ---------------- init ----------------
__global__ void k_zero() {
    int i = blockIdx.x*blockDim.x + threadIdx.x;
    if (i < BB*CC*HH*HH) g_fhat[i] = 0.f;
    if (i == 0) g_loss = 0.f;
}

__global__ void k_esq(const float* __restrict__ embed) {
    int v = blockIdx.x*blockDim.x + threadIdx.x;
    if (v < VV) {
        const float4* e4 = (const float4*)(embed + v*32);
        float s = 0.f;
        #pragma unroll
        for (int q = 0; q < 8; q++) {
            float4 a = e4[q];
            s = fmaf(a.x, a.x, s); s = fmaf(a.y, a.y, s);
            s = fmaf(a.z, a.z, s); s = fmaf(a.w, a.w, s);
        }
        g_esq[v] = s;
    }
}

// ---------------- residual + adaptive avg pool -> g_rest[n][c] ----------------
__global__ void k_pool(const float* __restrict__ f, int pn, int N) {
    int t = blockIdx.x*blockDim.x + threadIdx.x;
    if (t >= N*CC) return;
    int c = t & 31, n = t >> 5;
    int pp = pn*pn;
    int b = n / pp, r = n % pp, i = r / pn, j = r % pn;
    int s0 = (i*HH)/pn,  e0 = ((i+1)*HH + pn - 1)/pn;
    int s1 = (j*HH)/pn,  e1 = ((j+1)*HH + pn - 1)/pn;
    const float* fb = f      + ((b*CC + c) << 8);
    const float* hb = g_fhat + ((b*CC + c) << 8);
    float s = 0.f;
    for (int h = s0; h < e0; h++)
        for (int w = s1; w < e1; w++)
            s += fb[h*16 + w] - hb[h*16 + w];
    g_rest[n*32 + c] = s / (float)((e0 - s0) * (e1 - s1));
}

// ---------------- argmin phase 1 (templated): per-chunk best, f32x2 ----------------
template<int VPT, int CHKT>
__global__ __launch_bounds__(256) void k_dist_t(const float* __restrict__ embed, int N) {
    __shared__ ulonglong2 es[CHKT*8];   // CHKT codes x 128B
    __shared__ float ess[CHKT];
    int ck = blockIdx.y;
    int t  = threadIdx.x;
    {
        const float4* src = (const float4*)(embed + (ck*CHKT)*32);
        float4* dst = (float4*)es;
        #pragma unroll
        for (int q = t; q < CHKT*8; q += 256) dst[q] = src[q];
        for (int q = t; q < CHKT; q += 256) ess[q] = g_esq[ck*CHKT + q];
    }
    int n0 = blockIdx.x*(256*VPT) + t;
    int n1 = n0 + 256;
    bool v0 = (n0 < N);
    bool v1 = (VPT == 2) && (n1 < N);

    u64 x0p[16], x1p[16];
    #pragma unroll
    for (int q = 0; q < 16; q++) { x0p[q] = 0ull; x1p[q] = 0ull; }
    if (v0) {
        const ulonglong2* xp = (const ulonglong2*)(g_rest + n0*32);
        #pragma unroll
        for (int q = 0; q < 8; q++) { ulonglong2 a = xp[q]; x0p[2*q] = a.x; x0p[2*q+1] = a.y; }
    }
    if (VPT == 2 && v1) {
        const ulonglong2* xp = (const ulonglong2*)(g_rest + n1*32);
        #pragma unroll
        for (int q = 0; q < 8; q++) { ulonglong2 a = xp[q]; x1p[2*q] = a.x; x1p[2*q+1] = a.y; }
    }
    __syncthreads();
    if (!v0) return;

    float bd0 = 3.4e38f, bd1 = 3.4e38f;
    int   bi0 = 0,        bi1 = 0;
    for (int v = 0; v < CHKT; v++) {
        u64 a0 = 0ull, a0b = 0ull, a1 = 0ull, a1b = 0ull;
        #pragma unroll
        for (int q = 0; q < 8; q++) {
            ulonglong2 e = es[v*8 + q];
            fma2(a0,  x0p[2*q],   e.x);
            fma2(a0b, x0p[2*q+1], e.y);
            if (VPT == 2) {
                fma2(a1,  x1p[2*q],   e.x);
                fma2(a1b, x1p[2*q+1], e.y);
            }
        }
        float esv = ess[v];
        float2 f0 = upk2(a0), f0b = upk2(a0b);
        float dist0 = esv - 2.f*((f0.x + f0.y) + (f0b.x + f0b.y));
        if (dist0 < bd0) { bd0 = dist0; bi0 = v; }
        if (VPT == 2) {
            float2 f1 = upk2(a1), f1b = upk2(a1b);
            float dist1 = esv - 2.f*((f1.x + f1.y) + (f1b.x + f1b.y));
            if (dist1 < bd1) { bd1 = dist1; bi1 = v; }
        }
    }
    g_d1[ck*NMAX + n0] = bd0;  g_i1[ck*NMAX + n0] = ck*CHKT + bi0;
    if (VPT == 2 && v1) { g_d1[ck*NMAX + n1] = bd1;  g_i1[ck*NMAX + n1] = ck*CHKT + bi1; }
}

// ---------------- argmin phase 2: reduce chunks (first-occurrence tie-break) ----------------
__global__ void k_amin(int N, int nchunk) {
    int n = blockIdx.x*blockDim.x + threadIdx.x;
    if (n >= N) return;
    float bd = g_d1[n]; int bi = g_i1[n];
    for (int ck = 1; ck < nchunk; ck++) {
        float d = g_d1[ck*NMAX + n];
        if (d < bd) { bd = d; bi = g_i1[ck*NMAX + n]; }
    }
    g_idx[n] = bi;
}

// ---------------- gather + bilinear upsample + Phi conv + f_hat accum + loss ----------------
// grid = 256 blocks (4 per image: row bands of 4), 256 threads
__global__ __launch_bounds__(256) void k_phi(
    const float* __restrict__ f, const float* __restrict__ embed,
    const float* __restrict__ phi_w, const float* __restrict__ phi_b,
    int pn, int kidx)
{
    extern __shared__ float sm[];
    float* hpn = sm;            // 8192 floats  [p][c]
    float* hs  = sm + 8192;     // 3456 floats  [c][6][18]  (zero padded)
    float* ws  = hs + 3456;     // 9216 floats  [ci][dy][dx][co]
    float* red = ws + 9216;     // 256
    int t  = threadIdx.x;
    int b  = blockIdx.x >> 2;
    int r0 = (blockIdx.x & 3) * 4;
    int np = pn*pn;

    // weights: transpose OIHW -> [ci][dy][dx][co]
    for (int q = t; q < 9216; q += 256) {
        int co = q & 31, u = q >> 5;
        int dx = u % 3, dy = (u/3) % 3, ci = u/9;
        ws[q] = phi_w[kidx*9216 + ((co*32 + ci)*9 + dy*3 + dx)];
    }
    // gather selected codes
    for (int p = t; p < np; p += 256) {
        int id = g_idx[b*np + p];
        const float4* src = (const float4*)(embed + id*32);
        float4* dst = (float4*)(hpn + p*32);
        #pragma unroll
        for (int q = 0; q < 8; q++) dst[q] = src[q];
    }
    // zero padded tile
    for (int q = t; q < 3456; q += 256) hs[q] = 0.f;
    __syncthreads();

    // bilinear upsample (half-pixel, edge clamp): rows r0-1..r0+4 -> hs rows 0..5, cols 1..16
    if (t < 96) {
        int lr = t >> 4;       // 0..5
        int x  = t & 15;
        int gy = r0 - 1 + lr;
        if (gy >= 0 && gy < 16) {
            float sc = pn * 0.0625f;
            float sy = (gy + 0.5f) * sc - 0.5f;
            float y0f = floorf(sy);
            float fy = sy - y0f;
            int y0 = (int)y0f, y1i = y0 + 1;
            y0  = min(max(y0, 0), pn-1);
            y1i = min(max(y1i, 0), pn-1);
            float sx = (x + 0.5f) * sc - 0.5f;
            float x0f = floorf(sx);
            float fx = sx - x0f;
            int xx0 = (int)x0f, xx1 = xx0 + 1;
            xx0 = min(max(xx0, 0), pn-1);
            xx1 = min(max(xx1, 0), pn-1);
            float w00 = (1.f-fy)*(1.f-fx), w01 = (1.f-fy)*fx;
            float w10 = fy*(1.f-fx),       w11 = fy*fx;
            const float* p00 = hpn + (y0 *pn + xx0)*32;
            const float* p01 = hpn + (y0 *pn + xx1)*32;
            const float* p10 = hpn + (y1i*pn + xx0)*32;
            const float* p11 = hpn + (y1i*pn + xx1)*32;
            for (int c = 0; c < 32; c++) {
                float v = w00*p00[c] + w01*p01[c] + w10*p10[c] + w11*p11[c];
                hs[c*108 + lr*18 + (x+1)] = v;
            }
        }
    }
    __syncthreads();

    // conv3x3 (cross-correlation, zero pad): 8 output channels per thread, f32x2
    int px = t & 63;
    int ty = px >> 4, tx = px & 15;      // ty 0..3
    int co0 = (t >> 6) * 8;              // 0,8,16,24
    u64 acc[4];
    #pragma unroll
    for (int q = 0; q < 4; q++)
        acc[q] = *(const u64*)(phi_b + kidx*32 + co0 + 2*q);   // packed bias pair
    for (int ci = 0; ci < 32; ci++) {
        #pragma unroll
        for (int dy = 0; dy < 3; dy++) {
            #pragma unroll
            for (int dx = 0; dx < 3; dx++) {
                float hv = hs[ci*108 + (ty+dy)*18 + (tx+dx)];
                u64 hv2 = pk2(hv, hv);
                const ulonglong2* w2 = (const ulonglong2*)(ws + ((ci*3+dy)*3+dx)*32 + co0);
                ulonglong2 wa = w2[0], wb = w2[1];
                fma2(acc[0], hv2, wa.x);
                fma2(acc[1], hv2, wa.y);
                fma2(acc[2], hv2, wb.x);
                fma2(acc[3], hv2, wb.y);
            }
        }
    }
    // phi = 0.5*h + 0.5*(conv+b); accumulate f_hat; loss sse
    int y = r0 + ty;
    float sse = 0.f;
    #pragma unroll
    for (int q = 0; q < 4; q++) {
        float2 a = upk2(acc[q]);
        #pragma unroll
        for (int s = 0; s < 2; s++) {
            int co = co0 + 2*q + s;
            float cv = (s == 0) ? a.x : a.y;
            float hu = hs[co*108 + (ty+1)*18 + (tx+1)];
            float hphi = 0.5f*hu + 0.5f*cv;
            int off = ((b*32 + co) << 8) + y*16 + tx;
            float fh = g_fhat[off] + hphi;
            g_fhat[off] = fh;
            float d = fh - f[off];
            sse = fmaf(d, d, sse);
        }
    }
    red[t] = sse;
    __syncthreads();
    for (int s = 128; s > 0; s >>= 1) {
        if (t < s) red[t] += red[t + s];
        __syncthreads();
    }
    if (t == 0) atomicAdd(&g_loss, red[0]);
}

// ---------------- output ----------------
__global__ void k_out(float* __restrict__ out, int out_size) {
    int i = blockIdx.x*blockDim.x + threadIdx.x;
    if (i < out_size && i < BB*CC*HH*HH) out[i] = g_fhat[i];
    if (i == 0) {
        float lv = g_loss * (1.25f / (8.0f * 524288.0f));
        if (out_size > BB*CC*HH*HH) out[BB*CC*HH*HH] = lv;
        else if (out_size == 1)     out[0] = lv;
    }
}

// ---------------- launch ----------------
extern "C" void kernel_launch(void* const* d_in, const int* in_sizes, int n_in,
                              void* d_out, int out_size) {
    const float* f     = (const float*)d_in[0];
    const float* embed = (const float*)d_in[1];
    const float* phi_w = (const float*)d_in[2];
    const float* phi_b = (const float*)d_in[3];
    (void)in_sizes; (void)n_in;

    const int smem_phi = (8192 + 3456 + 9216 + 256) * 4;  // 84480 B
    cudaFuncSetAttribute(k_phi, cudaFuncAttributeMaxDynamicSharedMemorySize, smem_phi);

    static const int pns[8] = {1, 2, 4, 6, 8, 10, 13, 16};
    static const int kk [8] = {0, 0, 1, 1, 2, 2, 3, 3};

    k_zero<<<2048, 256>>>();
    k_esq<<<16, 256>>>(embed);

    for (int si = 0; si < 8; si++) {
        int pn = pns[si];
        int N  = BB * pn * pn;
        k_pool<<<(N*CC + 255)/256, 256>>>(f, pn, N);
        int nchunk;
        if (pn <= 6) {
            nchunk = 32;
            dim3 g1((N + 255)/256, 32);
            k_dist_t<1,128><<<g1, 256>>>(embed, N);
        } else {
            nchunk = 16;
            dim3 g1((N + 511)/512, 16);
            k_dist_t<2,256><<<g1, 256>>>(embed, N);
        }
        k_amin<<<(N + 255)/256, 256>>>(N, nchunk);
        k_phi<<<256, 256, smem_phi>>>(f, embed, phi_w, phi_b, pn, kk[si]);
    }
    k_out<<<2049, 256>>>((float*)d_out, out_size);
}

// round 5
// speedup vs baseline: 1.7757x; 1.1062x over previous
#include <cuda_runtime.h>
#include <math.h>

#define BB 64
#define CC 32
#define HH 16
#define VV 4096
#define NMAX 16384
#define NCHK 64          // chunks of 64 codes

typedef unsigned long long u64;

// ---------------- scratch ----------------
__device__ float g_fhat[BB*CC*HH*HH];
__device__ float g_rest[NMAX*CC];
__device__ float g_esq[VV];
__device__ float g_d1[NCHK*NMAX];    // 4MB
__device__ int   g_i1[NCHK*NMAX];    // 4MB
__device__ int   g_idx[NMAX];
__device__ float g_loss;

// ---------------- f32x2 helpers ----------------
__device__ __forceinline__ void fma2(u64& acc, u64 a, u64 b) {
    asm("fma.rn.f32x2 %0, %1, %2, %0;" : "+l"(acc) : "l"(a), "l"(b));
}
__device__ __forceinline__ u64 pk2(float lo, float hi) {
    u64 r; asm("mov.b64 %0, {%1,%2};" : "=l"(r) : "f"(lo), "f"(hi)); return r;
}
__device__ __forceinline__ float2 upk2(u64 v) {
    float2 f; asm("mov.b64 {%0,%1}, %2;" : "=f"(f.x), "=f"(f.y) : "l"(v)); return f;
}

// ---------------- init: zero fhat/loss + codebook norms ----------------
__global__ void k_init(const float* __restrict__ embed) {
    int i = blockIdx.x*blockDim.x + threadIdx.x;
    if (i < BB*CC*HH*HH) g_fhat[i] = 0.f;
    if (i == 0) g_loss = 0.f;
    if (i < VV) {
        const float4* e4 = (const float4*)(embed + i*32);
        float s = 0.f;
        #pragma unroll
        for (int q = 0; q < 8; q++) {
            float4 a = e4[q];
            s = fmaf(a.x, a.x, s); s = fmaf(a.y, a.y, s);
            s = fmaf(a.z, a.z, s); s = fmaf(a.w, a.w, s);
        }
        g_esq[i] = s;
    }
}

// ---------------- pool: warp per (n,c) for big windows (pn divides 16) ----------------
__global__ void k_pool_w(const float* __restrict__ f, int pn, int N) {
    int gw = (blockIdx.x*blockDim.x + threadIdx.x) >> 5;
    int lane = threadIdx.x & 31;
    if (gw >= N*CC) return;
    int c = gw & 31, n = gw >> 5;
    int pp = pn*pn;
    int b = n / pp, r = n % pp, i = r / pn, j = r % pn;
    int wh = HH / pn;                  // 16 or 8
    int npx = wh*wh;                   // 256 or 64
    int s0 = i*wh, s1 = j*wh;
    const float* fb = f      + ((b*CC + c) << 8);
    const float* hb = g_fhat + ((b*CC + c) << 8);
    float s = 0.f;
    for (int p = lane; p < npx; p += 32) {
        int h = s0 + p / wh, w = s1 + p % wh;
        s += fb[h*16 + w] - hb[h*16 + w];
    }
    #pragma unroll
    for (int o = 16; o > 0; o >>= 1) s += __shfl_down_sync(0xffffffffu, s, o);
    if (lane == 0) g_rest[n*32 + c] = s / (float)npx;
}

// ---------------- pool: thread per (n,c) for small windows ----------------
__global__ void k_pool(const float* __restrict__ f, int pn, int N) {
    int t = blockIdx.x*blockDim.x + threadIdx.x;
    if (t >= N*CC) return;
    int c = t & 31, n = t >> 5;
    int pp = pn*pn;
    int b = n / pp, r = n % pp, i = r / pn, j = r % pn;
    int s0 = (i*HH)/pn,  e0 = ((i+1)*HH + pn - 1)/pn;
    int s1 = (j*HH)/pn,  e1 = ((j+1)*HH + pn - 1)/pn;
    const float* fb = f      + ((b*CC + c) << 8);
    const float* hb = g_fhat + ((b*CC + c) << 8);
    float s = 0.f;
    for (int h = s0; h < e0; h++)
        for (int w = s1; w < e1; w++)
            s += fb[h*16 + w] - hb[h*16 + w];
    g_rest[n*32 + c] = s / (float)((e0 - s0) * (e1 - s1));
}

// ---------------- dist: 64-code chunk, 2 vectors/thread, f32x2 ----------------
__global__ __launch_bounds__(128) void k_dist(const float* __restrict__ embed, int N) {
    __shared__ ulonglong2 es[64*8];   // 8 KB
    __shared__ float ess[64];
    int ck = blockIdx.y;
    int t  = threadIdx.x;
    {
        const float4* src = (const float4*)(embed + (ck*64)*32);
        float4* dst = (float4*)es;
        #pragma unroll
        for (int q = t; q < 512; q += 128) dst[q] = src[q];
        if (t < 64) ess[t] = g_esq[ck*64 + t];
    }
    int n0 = blockIdx.x*256 + t;
    int n1 = n0 + 128;
    bool v0 = (n0 < N), v1 = (n1 < N);
    u64 x0p[16], x1p[16];
    #pragma unroll
    for (int q = 0; q < 16; q++) { x0p[q] = 0ull; x1p[q] = 0ull; }
    if (v0) {
        const ulonglong2* xp = (const ulonglong2*)(g_rest + n0*32);
        #pragma unroll
        for (int q = 0; q < 8; q++) { ulonglong2 a = xp[q]; x0p[2*q] = a.x; x0p[2*q+1] = a.y; }
    }
    if (v1) {
        const ulonglong2* xp = (const ulonglong2*)(g_rest + n1*32);
        #pragma unroll
        for (int q = 0; q < 8; q++) { ulonglong2 a = xp[q]; x1p[2*q] = a.x; x1p[2*q+1] = a.y; }
    }
    __syncthreads();
    if (!v0) return;
    float bd0 = 3.4e38f, bd1 = 3.4e38f;
    int   bi0 = 0,        bi1 = 0;
    #pragma unroll 2
    for (int v = 0; v < 64; v++) {
        u64 a0 = 0ull, a0b = 0ull, a1 = 0ull, a1b = 0ull;
        #pragma unroll
        for (int q = 0; q < 8; q++) {
            ulonglong2 e = es[v*8 + q];
            fma2(a0,  x0p[2*q],   e.x);
            fma2(a0b, x0p[2*q+1], e.y);
            fma2(a1,  x1p[2*q],   e.x);
            fma2(a1b, x1p[2*q+1], e.y);
        }
        float esv = ess[v];
        float2 f0 = upk2(a0), f0b = upk2(a0b);
        float dist0 = esv - 2.f*((f0.x + f0.y) + (f0b.x + f0b.y));
        if (dist0 < bd0) { bd0 = dist0; bi0 = v; }
        float2 f1 = upk2(a1), f1b = upk2(a1b);
        float dist1 = esv - 2.f*((f1.x + f1.y) + (f1b.x + f1b.y));
        if (dist1 < bd1) { bd1 = dist1; bi1 = v; }
    }
    g_d1[ck*NMAX + n0] = bd0;  g_i1[ck*NMAX + n0] = ck*64 + bi0;
    if (v1) { g_d1[ck*NMAX + n1] = bd1;  g_i1[ck*NMAX + n1] = ck*64 + bi1; }
}

// ---------------- argmin reduce over 64 chunks (first-occurrence ties) ----------------
__global__ void k_amin(int N) {
    int n = blockIdx.x*blockDim.x + threadIdx.x;
    if (n >= N) return;
    float bd = g_d1[n]; int bi = g_i1[n];
    #pragma unroll 8
    for (int ck = 1; ck < NCHK; ck++) {
        float d = g_d1[ck*NMAX + n];
        if (d < bd) { bd = d; bi = g_i1[ck*NMAX + n]; }
    }
    g_idx[n] = bi;
}

// ---------------- gather + bilinear upsample + Phi conv + f_hat accum + loss ----------------
__global__ __launch_bounds__(256) void k_phi(
    const float* __restrict__ f, const float* __restrict__ embed,
    const float* __restrict__ phi_w, const float* __restrict__ phi_b,
    int pn, int kidx)
{
    extern __shared__ float sm[];
    float* hpn = sm;            // 8192 [p][c]
    float* hs  = sm + 8192;     // 3456 [c][6][18] zero padded
    float* ws  = hs + 3456;     // 9216 [ci][dy][dx][co]
    float* red = ws + 9216;     // 256
    int t  = threadIdx.x;
    int b  = blockIdx.x >> 2;
    int r0 = (blockIdx.x & 3) * 4;
    int np = pn*pn;

    for (int q = t; q < 9216; q += 256) {
        int co = q & 31, u = q >> 5;
        int dx = u % 3, dy = (u/3) % 3, ci = u/9;
        ws[q] = phi_w[kidx*9216 + ((co*32 + ci)*9 + dy*3 + dx)];
    }
    for (int p = t; p < np; p += 256) {
        int id = g_idx[b*np + p];
        const float4* src = (const float4*)(embed + id*32);
        float4* dst = (float4*)(hpn + p*32);
        #pragma unroll
        for (int q = 0; q < 8; q++) dst[q] = src[q];
    }
    for (int q = t; q < 3456; q += 256) hs[q] = 0.f;
    __syncthreads();

    if (t < 96) {
        int lr = t >> 4;
        int x  = t & 15;
        int gy = r0 - 1 + lr;
        if (gy >= 0 && gy < 16) {
            float sc = pn * 0.0625f;
            float sy = (gy + 0.5f) * sc - 0.5f;
            float y0f = floorf(sy);
            float fy = sy - y0f;
            int y0 = (int)y0f, y1i = y0 + 1;
            y0  = min(max(y0, 0), pn-1);
            y1i = min(max(y1i, 0), pn-1);
            float sx = (x + 0.5f) * sc - 0.5f;
            float x0f = floorf(sx);
            float fx = sx - x0f;
            int xx0 = (int)x0f, xx1 = xx0 + 1;
            xx0 = min(max(xx0, 0), pn-1);
            xx1 = min(max(xx1, 0), pn-1);
            float w00 = (1.f-fy)*(1.f-fx), w01 = (1.f-fy)*fx;
            float w10 = fy*(1.f-fx),       w11 = fy*fx;
            const float* p00 = hpn + (y0 *pn + xx0)*32;
            const float* p01 = hpn + (y0 *pn + xx1)*32;
            const float* p10 = hpn + (y1i*pn + xx0)*32;
            const float* p11 = hpn + (y1i*pn + xx1)*32;
            for (int c = 0; c < 32; c++) {
                float v = w00*p00[c] + w01*p01[c] + w10*p10[c] + w11*p11[c];
                hs[c*108 + lr*18 + (x+1)] = v;
            }
        }
    }
    __syncthreads();

    int px = t & 63;
    int ty = px >> 4, tx = px & 15;
    int co0 = (t >> 6) * 8;
    u64 acc[4];
    #pragma unroll
    for (int q = 0; q < 4; q++)
        acc[q] = *(const u64*)(phi_b + kidx*32 + co0 + 2*q);
    for (int ci = 0; ci < 32; ci++) {
        #pragma unroll
        for (int dy = 0; dy < 3; dy++) {
            #pragma unroll
            for (int dx = 0; dx < 3; dx++) {
                float hv = hs[ci*108 + (ty+dy)*18 + (tx+dx)];
                u64 hv2 = pk2(hv, hv);
                const ulonglong2* w2 = (const ulonglong2*)(ws + ((ci*3+dy)*3+dx)*32 + co0);
                ulonglong2 wa = w2[0], wb = w2[1];
                fma2(acc[0], hv2, wa.x);
                fma2(acc[1], hv2, wa.y);
                fma2(acc[2], hv2, wb.x);
                fma2(acc[3], hv2, wb.y);
            }
        }
    }
    int y = r0 + ty;
    float sse = 0.f;
    #pragma unroll
    for (int q = 0; q < 4; q++) {
        float2 a = upk2(acc[q]);
        #pragma unroll
        for (int s = 0; s < 2; s++) {
            int co = co0 + 2*q + s;
            float cv = (s == 0) ? a.x : a.y;
            float hu = hs[co*108 + (ty+1)*18 + (tx+1)];
            float hphi = 0.5f*hu + 0.5f*cv;
            int off = ((b*32 + co) << 8) + y*16 + tx;
            float fh = g_fhat[off] + hphi;
            g_fhat[off] = fh;
            float d = fh - f[off];
            sse = fmaf(d, d, sse);
        }
    }
    red[t] = sse;
    __syncthreads();
    for (int s = 128; s > 0; s >>= 1) {
        if (t < s) red[t] += red[t + s];
        __syncthreads();
    }
    if (t == 0) atomicAdd(&g_loss, red[0]);
}

// ---------------- output ----------------
__global__ void k_out(float* __restrict__ out, int out_size) {
    int i = blockIdx.x*blockDim.x + threadIdx.x;
    if (i < out_size && i < BB*CC*HH*HH) out[i] = g_fhat[i];
    if (i == 0) {
        float lv = g_loss * (1.25f / (8.0f * 524288.0f));
        if (out_size > BB*CC*HH*HH) out[BB*CC*HH*HH] = lv;
        else if (out_size == 1)     out[0] = lv;
    }
}

// ---------------- launch ----------------
extern "C" void kernel_launch(void* const* d_in, const int* in_sizes, int n_in,
                              void* d_out, int out_size) {
    const float* f     = (const float*)d_in[0];
    const float* embed = (const float*)d_in[1];
    const float* phi_w = (const float*)d_in[2];
    const float* phi_b = (const float*)d_in[3];
    (void)in_sizes; (void)n_in;

    const int smem_phi = (8192 + 3456 + 9216 + 256) * 4;  // 84480 B
    cudaFuncSetAttribute(k_phi, cudaFuncAttributeMaxDynamicSharedMemorySize, smem_phi);

    static const int pns[8] = {1, 2, 4, 6, 8, 10, 13, 16};
    static const int kk [8] = {0, 0, 1, 1, 2, 2, 3, 3};

    k_init<<<2048, 256>>>(embed);

    for (int si = 0; si < 8; si++) {
        int pn = pns[si];
        int N  = BB * pn * pn;
        if (pn <= 2) {
            int nwarp = N * CC;                       // one warp per (n,c)
            k_pool_w<<<(nwarp*32 + 255)/256, 256>>>(f, pn, N);
        } else {
            k_pool<<<(N*CC + 255)/256, 256>>>(f, pn, N);
        }
        dim3 g1((N + 255)/256, NCHK);
        k_dist<<<g1, 128>>>(embed, N);
        k_amin<<<(N + 255)/256, 256>>>(N);
        k_phi<<<256, 256, smem_phi>>>(f, embed, phi_w, phi_b, pn, kk[si]);
    }
    k_out<<<2049, 256>>>((float*)d_out, out_size);
}

// round 6
// speedup vs baseline: 1.8641x; 1.0498x over previous
#include <cuda_runtime.h>
#include <math.h>

#define BB 64
#define CC 32
#define HH 16
#define VV 4096
#define NMAX 16384
#define NCHK 64          // chunks of 64 codes

typedef unsigned long long u64;

// ---------------- scratch ----------------
__device__ float g_fhat[BB*CC*HH*HH];
__device__ float g_rest[NMAX*CC];
__device__ float g_esq[VV];          // holds -0.5*|e|^2
__device__ float g_d1[NCHK*NMAX];    // per-chunk best val (bigger = closer)
__device__ int   g_i1[NCHK*NMAX];
__device__ float g_loss;

// ---------------- f32x2 helpers ----------------
__device__ __forceinline__ void fma2(u64& acc, u64 a, u64 b) {
    asm("fma.rn.f32x2 %0, %1, %2, %0;" : "+l"(acc) : "l"(a), "l"(b));
}
__device__ __forceinline__ u64 add2(u64 a, u64 b) {
    u64 r; asm("add.rn.f32x2 %0, %1, %2;" : "=l"(r) : "l"(a), "l"(b)); return r;
}
__device__ __forceinline__ u64 pk2(float lo, float hi) {
    u64 r; asm("mov.b64 %0, {%1,%2};" : "=l"(r) : "f"(lo), "f"(hi)); return r;
}
__device__ __forceinline__ float2 upk2(u64 v) {
    float2 f; asm("mov.b64 {%0,%1}, %2;" : "=f"(f.x), "=f"(f.y) : "l"(v)); return f;
}

// ---------------- init: zero fhat/loss + codebook norms (-0.5*|e|^2) ----------------
__global__ void k_init(const float* __restrict__ embed) {
    int i = blockIdx.x*blockDim.x + threadIdx.x;
    if (i < BB*CC*HH*HH) g_fhat[i] = 0.f;
    if (i == 0) g_loss = 0.f;
    if (i < VV) {
        const float4* e4 = (const float4*)(embed + i*32);
        float s = 0.f;
        #pragma unroll
        for (int q = 0; q < 8; q++) {
            float4 a = e4[q];
            s = fmaf(a.x, a.x, s); s = fmaf(a.y, a.y, s);
            s = fmaf(a.z, a.z, s); s = fmaf(a.w, a.w, s);
        }
        g_esq[i] = -0.5f * s;
    }
}

// ---------------- pool: warp per (n,c) for big windows ----------------
__global__ void k_pool_w(const float* __restrict__ f, int pn, int N) {
    int gw = (blockIdx.x*blockDim.x + threadIdx.x) >> 5;
    int lane = threadIdx.x & 31;
    if (gw >= N*CC) return;
    int c = gw & 31, n = gw >> 5;
    int pp = pn*pn;
    int b = n / pp, r = n % pp, i = r / pn, j = r % pn;
    int wh = HH / pn;
    int npx = wh*wh;
    int s0 = i*wh, s1 = j*wh;
    const float* fb = f      + ((b*CC + c) << 8);
    const float* hb = g_fhat + ((b*CC + c) << 8);
    float s = 0.f;
    for (int p = lane; p < npx; p += 32) {
        int h = s0 + p / wh, w = s1 + p % wh;
        s += fb[h*16 + w] - hb[h*16 + w];
    }
    #pragma unroll
    for (int o = 16; o > 0; o >>= 1) s += __shfl_down_sync(0xffffffffu, s, o);
    if (lane == 0) g_rest[n*32 + c] = s / (float)npx;
}

// ---------------- pool: thread per (n,c) ----------------
__global__ void k_pool(const float* __restrict__ f, int pn, int N) {
    int t = blockIdx.x*blockDim.x + threadIdx.x;
    if (t >= N*CC) return;
    int c = t & 31, n = t >> 5;
    int pp = pn*pn;
    int b = n / pp, r = n % pp, i = r / pn, j = r % pn;
    int s0 = (i*HH)/pn,  e0 = ((i+1)*HH + pn - 1)/pn;
    int s1 = (j*HH)/pn,  e1 = ((j+1)*HH + pn - 1)/pn;
    const float* fb = f      + ((b*CC + c) << 8);
    const float* hb = g_fhat + ((b*CC + c) << 8);
    float s = 0.f;
    for (int h = s0; h < e0; h++)
        for (int w = s1; w < e1; w++)
            s += fb[h*16 + w] - hb[h*16 + w];
    g_rest[n*32 + c] = s / (float)((e0 - s0) * (e1 - s1));
}

// ---------------- dist: 64-code chunk, VPT vectors/thread, f32x2 ----------------
// val = dot(x,e) - 0.5*|e|^2 ; maximize (equiv to min distance, same tie order)
template<int VPT>
__global__ __launch_bounds__(128) void k_dist(const float* __restrict__ embed, int N) {
    __shared__ ulonglong2 es[64*8];   // 8 KB
    __shared__ float ess[64];
    int ck = blockIdx.y;
    int t  = threadIdx.x;
    {
        const float4* src = (const float4*)(embed + (ck*64)*32);
        float4* dst = (float4*)es;
        #pragma unroll
        for (int q = t; q < 512; q += 128) dst[q] = src[q];
        if (t < 64) ess[t] = g_esq[ck*64 + t];
    }
    int nn[VPT]; bool vv[VPT];
    u64 x[VPT][16];
    #pragma unroll
    for (int s = 0; s < VPT; s++) {
        nn[s] = blockIdx.x*(128*VPT) + s*128 + t;
        vv[s] = (nn[s] < N);
        #pragma unroll
        for (int q = 0; q < 16; q++) x[s][q] = 0ull;
        if (vv[s]) {
            const ulonglong2* xp = (const ulonglong2*)(g_rest + nn[s]*32);
            #pragma unroll
            for (int q = 0; q < 8; q++) { ulonglong2 a = xp[q]; x[s][2*q] = a.x; x[s][2*q+1] = a.y; }
        }
    }
    __syncthreads();
    if (!vv[0]) return;
    float bv[VPT]; int bi[VPT];
    #pragma unroll
    for (int s = 0; s < VPT; s++) { bv[s] = -3.4e38f; bi[s] = 0; }
    #pragma unroll 2
    for (int v = 0; v < 64; v++) {
        u64 a0[VPT], a1[VPT];
        #pragma unroll
        for (int s = 0; s < VPT; s++) { a0[s] = 0ull; a1[s] = 0ull; }
        #pragma unroll
        for (int q = 0; q < 8; q++) {
            ulonglong2 e = es[v*8 + q];
            #pragma unroll
            for (int s = 0; s < VPT; s++) {
                fma2(a0[s], x[s][2*q],   e.x);
                fma2(a1[s], x[s][2*q+1], e.y);
            }
        }
        float esv = ess[v];
        #pragma unroll
        for (int s = 0; s < VPT; s++) {
            float2 f2 = upk2(add2(a0[s], a1[s]));
            float val = (f2.x + f2.y) + esv;
            if (val > bv[s]) { bv[s] = val; bi[s] = v; }
        }
    }
    #pragma unroll
    for (int s = 0; s < VPT; s++)
        if (vv[s]) { g_d1[ck*NMAX + nn[s]] = bv[s];  g_i1[ck*NMAX + nn[s]] = ck*64 + bi[s]; }
}

// ---------------- gather(+argmin) + upsample + Phi conv + f_hat accum + loss ----------------
__global__ __launch_bounds__(256) void k_phi(
    const float* __restrict__ f, const float* __restrict__ embed,
    const float* __restrict__ phi_w, const float* __restrict__ phi_b,
    int pn, int kidx)
{
    extern __shared__ float sm[];
    float* hpn = sm;            // 8192 [p][c]
    float* hs  = sm + 8192;     // 3456 [c][6][18] zero padded
    float* ws  = hs + 3456;     // 9216 [ci][dy][dx][co]
    float* red = ws + 9216;     // 256
    int t  = threadIdx.x;
    int b  = blockIdx.x >> 2;
    int r0 = (blockIdx.x & 3) * 4;
    int np = pn*pn;

    for (int q = t; q < 9216; q += 256) {
        int co = q & 31, u = q >> 5;
        int dx = u % 3, dy = (u/3) % 3, ci = u/9;
        ws[q] = phi_w[kidx*9216 + ((co*32 + ci)*9 + dy*3 + dx)];
    }
    // fused 64-chunk argmin + gather
    for (int p = t; p < np; p += 256) {
        int base = b*np + p;
        float bv = g_d1[base]; int bi = g_i1[base];
        #pragma unroll 8
        for (int ck = 1; ck < NCHK; ck++) {
            float v = g_d1[ck*NMAX + base];
            if (v > bv) { bv = v; bi = g_i1[ck*NMAX + base]; }
        }
        const float4* src = (const float4*)(embed + bi*32);
        float4* dst = (float4*)(hpn + p*32);
        #pragma unroll
        for (int q = 0; q < 8; q++) dst[q] = src[q];
    }
    for (int q = t; q < 3456; q += 256) hs[q] = 0.f;
    __syncthreads();

    if (t < 96) {
        int lr = t >> 4;
        int x  = t & 15;
        int gy = r0 - 1 + lr;
        if (gy >= 0 && gy < 16) {
            float sc = pn * 0.0625f;
            float sy = (gy + 0.5f) * sc - 0.5f;
            float y0f = floorf(sy);
            float fy = sy - y0f;
            int y0 = (int)y0f, y1i = y0 + 1;
            y0  = min(max(y0, 0), pn-1);
            y1i = min(max(y1i, 0), pn-1);
            float sx = (x + 0.5f) * sc - 0.5f;
            float x0f = floorf(sx);
            float fx = sx - x0f;
            int xx0 = (int)x0f, xx1 = xx0 + 1;
            xx0 = min(max(xx0, 0), pn-1);
            xx1 = min(max(xx1, 0), pn-1);
            float w00 = (1.f-fy)*(1.f-fx), w01 = (1.f-fy)*fx;
            float w10 = fy*(1.f-fx),       w11 = fy*fx;
            const float* p00 = hpn + (y0 *pn + xx0)*32;
            const float* p01 = hpn + (y0 *pn + xx1)*32;
            const float* p10 = hpn + (y1i*pn + xx0)*32;
            const float* p11 = hpn + (y1i*pn + xx1)*32;
            for (int c = 0; c < 32; c++) {
                float v = w00*p00[c] + w01*p01[c] + w10*p10[c] + w11*p11[c];
                hs[c*108 + lr*18 + (x+1)] = v;
            }
        }
    }
    __syncthreads();

    int px = t & 63;
    int ty = px >> 4, tx = px & 15;
    int co0 = (t >> 6) * 8;
    u64 acc[4];
    #pragma unroll
    for (int q = 0; q < 4; q++)
        acc[q] = *(const u64*)(phi_b + kidx*32 + co0 + 2*q);
    for (int ci = 0; ci < 32; ci++) {
        #pragma unroll
        for (int dy = 0; dy < 3; dy++) {
            #pragma unroll
            for (int dx = 0; dx < 3; dx++) {
                float hv = hs[ci*108 + (ty+dy)*18 + (tx+dx)];
                u64 hv2 = pk2(hv, hv);
                const ulonglong2* w2 = (const ulonglong2*)(ws + ((ci*3+dy)*3+dx)*32 + co0);
                ulonglong2 wa = w2[0], wb = w2[1];
                fma2(acc[0], hv2, wa.x);
                fma2(acc[1], hv2, wa.y);
                fma2(acc[2], hv2, wb.x);
                fma2(acc[3], hv2, wb.y);
            }
        }
    }
    int y = r0 + ty;
    float sse = 0.f;
    #pragma unroll
    for (int q = 0; q < 4; q++) {
        float2 a = upk2(acc[q]);
        #pragma unroll
        for (int s = 0; s < 2; s++) {
            int co = co0 + 2*q + s;
            float cv = (s == 0) ? a.x : a.y;
            float hu = hs[co*108 + (ty+1)*18 + (tx+1)];
            float hphi = 0.5f*hu + 0.5f*cv;
            int off = ((b*32 + co) << 8) + y*16 + tx;
            float fh = g_fhat[off] + hphi;
            g_fhat[off] = fh;
            float d = fh - f[off];
            sse = fmaf(d, d, sse);
        }
    }
    red[t] = sse;
    __syncthreads();
    for (int s = 128; s > 0; s >>= 1) {
        if (t < s) red[t] += red[t + s];
        __syncthreads();
    }
    if (t == 0) atomicAdd(&g_loss, red[0]);
}

// ---------------- output ----------------
__global__ void k_out(float* __restrict__ out, int out_size) {
    int i = blockIdx.x*blockDim.x + threadIdx.x;
    if (i < out_size && i < BB*CC*HH*HH) out[i] = g_fhat[i];
    if (i == 0) {
        float lv = g_loss * (1.25f / (8.0f * 524288.0f));
        if (out_size > BB*CC*HH*HH) out[BB*CC*HH*HH] = lv;
        else if (out_size == 1)     out[0] = lv;
    }
}

// ---------------- launch ----------------
extern "C" void kernel_launch(void* const* d_in, const int* in_sizes, int n_in,
                              void* d_out, int out_size) {
    const float* f     = (const float*)d_in[0];
    const float* embed = (const float*)d_in[1];
    const float* phi_w = (const float*)d_in[2];
    const float* phi_b = (const float*)d_in[3];
    (void)in_sizes; (void)n_in;

    const int smem_phi = (8192 + 3456 + 9216 + 256) * 4;  // 84480 B
    cudaFuncSetAttribute(k_phi, cudaFuncAttributeMaxDynamicSharedMemorySize, smem_phi);

    static const int pns[8] = {1, 2, 4, 6, 8, 10, 13, 16};
    static const int kk [8] = {0, 0, 1, 1, 2, 2, 3, 3};

    k_init<<<2048, 256>>>(embed);

    for (int si = 0; si < 8; si++) {
        int pn = pns[si];
        int N  = BB * pn * pn;
        if (pn <= 2) {
            int nwarp = N * CC;
            k_pool_w<<<(nwarp*32 + 255)/256, 256>>>(f, pn, N);
        } else {
            k_pool<<<(N*CC + 255)/256, 256>>>(f, pn, N);
        }
        if (pn >= 8) {
            dim3 g1((N + 511)/512, NCHK);
            k_dist<4><<<g1, 128>>>(embed, N);
        } else {
            dim3 g1((N + 255)/256, NCHK);
            k_dist<2><<<g1, 128>>>(embed, N);
        }
        k_phi<<<256, 256, smem_phi>>>(f, embed, phi_w, phi_b, pn, kk[si]);
    }
    k_out<<<2049, 256>>>((float*)d_out, out_size);
}

// round 7
// speedup vs baseline: 2.0714x; 1.1112x over previous
#include <cuda_runtime.h>
#include <math.h>

#define BB 64
#define CC 32
#define HH 16
#define VV 4096
#define NMAX 16384
#define NCHK 64          // chunks of 64 codes

typedef unsigned long long u64;

// ---------------- scratch ----------------
__device__ float g_fhat[BB*CC*HH*HH];
__device__ float g_rest[NMAX*CC];
__device__ float g_esq[VV];          // holds -0.5*|e|^2
__device__ float g_d1[NCHK*NMAX];    // per-chunk best val (bigger = closer)
__device__ int   g_i1[NCHK*NMAX];
__device__ float g_wsT[4*9216];      // transposed weights [k][ci*9+pos][co]
__device__ float g_loss;

// ---------------- f32x2 helpers ----------------
__device__ __forceinline__ void fma2(u64& acc, u64 a, u64 b) {
    asm("fma.rn.f32x2 %0, %1, %2, %0;" : "+l"(acc) : "l"(a), "l"(b));
}
__device__ __forceinline__ u64 add2(u64 a, u64 b) {
    u64 r; asm("add.rn.f32x2 %0, %1, %2;" : "=l"(r) : "l"(a), "l"(b)); return r;
}
__device__ __forceinline__ u64 pk2(float lo, float hi) {
    u64 r; asm("mov.b64 %0, {%1,%2};" : "=l"(r) : "f"(lo), "f"(hi)); return r;
}
__device__ __forceinline__ float2 upk2(u64 v) {
    float2 f; asm("mov.b64 {%0,%1}, %2;" : "=f"(f.x), "=f"(f.y) : "l"(v)); return f;
}

// ---------------- init: zero fhat/loss + codebook norms + weight transpose ----------------
__global__ void k_init(const float* __restrict__ embed, const float* __restrict__ phi_w) {
    int i = blockIdx.x*blockDim.x + threadIdx.x;
    if (i < BB*CC*HH*HH) g_fhat[i] = 0.f;
    if (i == 0) g_loss = 0.f;
    if (i < VV) {
        const float4* e4 = (const float4*)(embed + i*32);
        float s = 0.f;
        #pragma unroll
        for (int q = 0; q < 8; q++) {
            float4 a = e4[q];
            s = fmaf(a.x, a.x, s); s = fmaf(a.y, a.y, s);
            s = fmaf(a.z, a.z, s); s = fmaf(a.w, a.w, s);
        }
        g_esq[i] = -0.5f * s;
    }
    if (i < 4*9216) {
        int co = i & 31;
        int u  = (i >> 5) % 288;     // ci*9 + dy*3 + dx
        int k  = i / 9216;
        int dx = u % 3, dy = (u/3) % 3, ci = u/9;
        g_wsT[i] = phi_w[k*9216 + ((co*32 + ci)*9 + dy*3 + dx)];
    }
}

// ---------------- pool: warp per (n,c) for big windows ----------------
__global__ void k_pool_w(const float* __restrict__ f, int pn, int N) {
    int gw = (blockIdx.x*blockDim.x + threadIdx.x) >> 5;
    int lane = threadIdx.x & 31;
    if (gw >= N*CC) return;
    int c = gw & 31, n = gw >> 5;
    int pp = pn*pn;
    int b = n / pp, r = n % pp, i = r / pn, j = r % pn;
    int wh = HH / pn;
    int npx = wh*wh;
    int s0 = i*wh, s1 = j*wh;
    const float* fb = f      + ((b*CC + c) << 8);
    const float* hb = g_fhat + ((b*CC + c) << 8);
    float s = 0.f;
    for (int p = lane; p < npx; p += 32) {
        int h = s0 + p / wh, w = s1 + p % wh;
        s += fb[h*16 + w] - hb[h*16 + w];
    }
    #pragma unroll
    for (int o = 16; o > 0; o >>= 1) s += __shfl_down_sync(0xffffffffu, s, o);
    if (lane == 0) g_rest[n*32 + c] = s / (float)npx;
}

// ---------------- pool: thread per (n,c) ----------------
__global__ void k_pool(const float* __restrict__ f, int pn, int N) {
    int t = blockIdx.x*blockDim.x + threadIdx.x;
    if (t >= N*CC) return;
    int c = t & 31, n = t >> 5;
    int pp = pn*pn;
    int b = n / pp, r = n % pp, i = r / pn, j = r % pn;
    int s0 = (i*HH)/pn,  e0 = ((i+1)*HH + pn - 1)/pn;
    int s1 = (j*HH)/pn,  e1 = ((j+1)*HH + pn - 1)/pn;
    const float* fb = f      + ((b*CC + c) << 8);
    const float* hb = g_fhat + ((b*CC + c) << 8);
    float s = 0.f;
    for (int h = s0; h < e0; h++)
        for (int w = s1; w < e1; w++)
            s += fb[h*16 + w] - hb[h*16 + w];
    g_rest[n*32 + c] = s / (float)((e0 - s0) * (e1 - s1));
}

// ---------------- dist: 64-code chunk, VPT vectors/thread, f32x2 ----------------
// val = dot(x,e) - 0.5*|e|^2 ; maximize (equiv to min distance, same tie order)
template<int VPT>
__global__ __launch_bounds__(128) void k_dist(const float* __restrict__ embed, int N) {
    __shared__ ulonglong2 es[64*8];   // 8 KB
    __shared__ float ess[64];
    int ck = blockIdx.y;
    int t  = threadIdx.x;
    {
        const float4* src = (const float4*)(embed + (ck*64)*32);
        float4* dst = (float4*)es;
        #pragma unroll
        for (int q = t; q < 512; q += 128) dst[q] = src[q];
        if (t < 64) ess[t] = g_esq[ck*64 + t];
    }
    int nn[VPT]; bool vv[VPT];
    u64 x[VPT][16];
    #pragma unroll
    for (int s = 0; s < VPT; s++) {
        nn[s] = blockIdx.x*(128*VPT) + s*128 + t;
        vv[s] = (nn[s] < N);
        #pragma unroll
        for (int q = 0; q < 16; q++) x[s][q] = 0ull;
        if (vv[s]) {
            const ulonglong2* xp = (const ulonglong2*)(g_rest + nn[s]*32);
            #pragma unroll
            for (int q = 0; q < 8; q++) { ulonglong2 a = xp[q]; x[s][2*q] = a.x; x[s][2*q+1] = a.y; }
        }
    }
    __syncthreads();
    if (!vv[0]) return;
    float bv[VPT]; int bi[VPT];
    #pragma unroll
    for (int s = 0; s < VPT; s++) { bv[s] = -3.4e38f; bi[s] = 0; }
    #pragma unroll 2
    for (int v = 0; v < 64; v++) {
        u64 a0[VPT], a1[VPT];
        #pragma unroll
        for (int s = 0; s < VPT; s++) { a0[s] = 0ull; a1[s] = 0ull; }
        #pragma unroll
        for (int q = 0; q < 8; q++) {
            ulonglong2 e = es[v*8 + q];
            #pragma unroll
            for (int s = 0; s < VPT; s++) {
                fma2(a0[s], x[s][2*q],   e.x);
                fma2(a1[s], x[s][2*q+1], e.y);
            }
        }
        float esv = ess[v];
        #pragma unroll
        for (int s = 0; s < VPT; s++) {
            float2 f2 = upk2(add2(a0[s], a1[s]));
            float val = (f2.x + f2.y) + esv;
            if (val > bv[s]) { bv[s] = val; bi[s] = v; }
        }
    }
    #pragma unroll
    for (int s = 0; s < VPT; s++)
        if (vv[s]) { g_d1[ck*NMAX + nn[s]] = bv[s];  g_i1[ck*NMAX + nn[s]] = ck*64 + bi[s]; }
}

// ---------------- gather(+argmin) + upsample + Phi conv + f_hat accum + loss ----------------
// smem: hpn/ws union (9216) + hs (3456) + red (256) = 12928 floats = 51712 B -> 4 blocks/SM
__global__ __launch_bounds__(256) void k_phi(
    const float* __restrict__ f, const float* __restrict__ embed,
    const float* __restrict__ phi_b,
    int pn, int kidx)
{
    extern __shared__ float sm[];
    float* hpn = sm;            // [p][c] (phase A)
    float* ws  = sm;            // [ci][dy][dx][co] (phase B, aliases hpn)
    float* hs  = sm + 9216;     // 3456 [c][6][18] zero padded
    float* red = hs + 3456;     // 256
    int t  = threadIdx.x;
    int b  = blockIdx.x >> 2;
    int r0 = (blockIdx.x & 3) * 4;
    int np = pn*pn;

    // phase A: fused 64-chunk argmin + gather codes into hpn
    for (int p = t; p < np; p += 256) {
        int base = b*np + p;
        float bv = g_d1[base]; int bi = g_i1[base];
        #pragma unroll 8
        for (int ck = 1; ck < NCHK; ck++) {
            float v = g_d1[ck*NMAX + base];
            if (v > bv) { bv = v; bi = g_i1[ck*NMAX + base]; }
        }
        const float4* src = (const float4*)(embed + bi*32);
        float4* dst = (float4*)(hpn + p*32);
        #pragma unroll
        for (int q = 0; q < 8; q++) dst[q] = src[q];
    }
    for (int q = t; q < 3456; q += 256) hs[q] = 0.f;
    __syncthreads();

    // upsample hpn -> hs
    if (t < 96) {
        int lr = t >> 4;
        int x  = t & 15;
        int gy = r0 - 1 + lr;
        if (gy >= 0 && gy < 16) {
            float sc = pn * 0.0625f;
            float sy = (gy + 0.5f) * sc - 0.5f;
            float y0f = floorf(sy);
            float fy = sy - y0f;
            int y0 = (int)y0f, y1i = y0 + 1;
            y0  = min(max(y0, 0), pn-1);
            y1i = min(max(y1i, 0), pn-1);
            float sx = (x + 0.5f) * sc - 0.5f;
            float x0f = floorf(sx);
            float fx = sx - x0f;
            int xx0 = (int)x0f, xx1 = xx0 + 1;
            xx0 = min(max(xx0, 0), pn-1);
            xx1 = min(max(xx1, 0), pn-1);
            float w00 = (1.f-fy)*(1.f-fx), w01 = (1.f-fy)*fx;
            float w10 = fy*(1.f-fx),       w11 = fy*fx;
            const float* p00 = hpn + (y0 *pn + xx0)*32;
            const float* p01 = hpn + (y0 *pn + xx1)*32;
            const float* p10 = hpn + (y1i*pn + xx0)*32;
            const float* p11 = hpn + (y1i*pn + xx1)*32;
            for (int c = 0; c < 32; c++) {
                float v = w00*p00[c] + w01*p01[c] + w10*p10[c] + w11*p11[c];
                hs[c*108 + lr*18 + (x+1)] = v;
            }
        }
    }
    __syncthreads();

    // phase B: load pre-transposed weights (overwrites hpn)
    {
        const float4* src = (const float4*)(g_wsT + kidx*9216);
        float4* dst = (float4*)ws;
        #pragma unroll
        for (int q = t; q < 2304; q += 256) dst[q] = src[q];
    }
    __syncthreads();

    // conv3x3 (cross-correlation, zero pad): 8 co per thread, f32x2
    int px = t & 63;
    int ty = px >> 4, tx = px & 15;
    int co0 = (t >> 6) * 8;
    u64 acc[4];
    #pragma unroll
    for (int q = 0; q < 4; q++)
        acc[q] = *(const u64*)(phi_b + kidx*32 + co0 + 2*q);
    for (int ci = 0; ci < 32; ci++) {
        #pragma unroll
        for (int dy = 0; dy < 3; dy++) {
            #pragma unroll
            for (int dx = 0; dx < 3; dx++) {
                float hv = hs[ci*108 + (ty+dy)*18 + (tx+dx)];
                u64 hv2 = pk2(hv, hv);
                const ulonglong2* w2 = (const ulonglong2*)(ws + ((ci*3+dy)*3+dx)*32 + co0);
                ulonglong2 wa = w2[0], wb = w2[1];
                fma2(acc[0], hv2, wa.x);
                fma2(acc[1], hv2, wa.y);
                fma2(acc[2], hv2, wb.x);
                fma2(acc[3], hv2, wb.y);
            }
        }
    }
    int y = r0 + ty;
    float sse = 0.f;
    #pragma unroll
    for (int q = 0; q < 4; q++) {
        float2 a = upk2(acc[q]);
        #pragma unroll
        for (int s = 0; s < 2; s++) {
            int co = co0 + 2*q + s;
            float cv = (s == 0) ? a.x : a.y;
            float hu = hs[co*108 + (ty+1)*18 + (tx+1)];
            float hphi = 0.5f*hu + 0.5f*cv;
            int off = ((b*32 + co) << 8) + y*16 + tx;
            float fh = g_fhat[off] + hphi;
            g_fhat[off] = fh;
            float d = fh - f[off];
            sse = fmaf(d, d, sse);
        }
    }
    red[t] = sse;
    __syncthreads();
    for (int s = 128; s > 0; s >>= 1) {
        if (t < s) red[t] += red[t + s];
        __syncthreads();
    }
    if (t == 0) atomicAdd(&g_loss, red[0]);
}

// ---------------- output ----------------
__global__ void k_out(float* __restrict__ out, int out_size) {
    int i = blockIdx.x*blockDim.x + threadIdx.x;
    if (i < out_size && i < BB*CC*HH*HH) out[i] = g_fhat[i];
    if (i == 0) {
        float lv = g_loss * (1.25f / (8.0f * 524288.0f));
        if (out_size > BB*CC*HH*HH) out[BB*CC*HH*HH] = lv;
        else if (out_size == 1)     out[0] = lv;
    }
}

// ---------------- launch ----------------
extern "C" void kernel_launch(void* const* d_in, const int* in_sizes, int n_in,
                              void* d_out, int out_size) {
    const float* f     = (const float*)d_in[0];
    const float* embed = (const float*)d_in[1];
    const float* phi_w = (const float*)d_in[2];
    const float* phi_b = (const float*)d_in[3];
    (void)in_sizes; (void)n_in;

    const int smem_phi = (9216 + 3456 + 256) * 4;  // 51712 B
    cudaFuncSetAttribute(k_phi, cudaFuncAttributeMaxDynamicSharedMemorySize, smem_phi);

    static const int pns[8] = {1, 2, 4, 6, 8, 10, 13, 16};
    static const int kk [8] = {0, 0, 1, 1, 2, 2, 3, 3};

    k_init<<<2048, 256>>>(embed, phi_w);

    for (int si = 0; si < 8; si++) {
        int pn = pns[si];
        int N  = BB * pn * pn;
        if (pn <= 2) {
            int nwarp = N * CC;
            k_pool_w<<<(nwarp*32 + 255)/256, 256>>>(f, pn, N);
        } else {
            k_pool<<<(N*CC + 255)/256, 256>>>(f, pn, N);
        }
        if (pn >= 8) {
            dim3 g1((N + 511)/512, NCHK);
            k_dist<4><<<g1, 128>>>(embed, N);
        } else {
            dim3 g1((N + 255)/256, NCHK);
            k_dist<2><<<g1, 128>>>(embed, N);
        }
        k_phi<<<256, 256, smem_phi>>>(f, embed, phi_b, pn, kk[si]);
    }
    k_out<<<2049, 256>>>((float*)d_out, out_size);
}